// round 6
// baseline (speedup 1.0000x reference)
#include <cuda_runtime.h>
#include <math.h>

// ---------------- problem constants ----------------
#define BSZ   8
#define MSEQ  1024
#define HDIM  1024
#define NHEAD 16
#define HDHD  64
#define HU    256
#define TOK   (BSZ*MSEQ)          // 8192

typedef unsigned long long ull;

// ---- packed fp32x2 helpers (sm_103a FFMA2 path) ----
__device__ __forceinline__ void ffma2(ull &d, ull a, ull b) {
    asm("fma.rn.f32x2 %0, %1, %2, %0;" : "+l"(d) : "l"(a), "l"(b));
}
__device__ __forceinline__ ull fdup(float x) {
    ull r; unsigned u = __float_as_uint(x);
    asm("mov.b64 %0, {%1, %1};" : "=l"(r) : "r"(u)); return r;
}
__device__ __forceinline__ ull fpack(float lo, float hi) {
    ull r; unsigned a = __float_as_uint(lo), b = __float_as_uint(hi);
    asm("mov.b64 %0, {%1, %2};" : "=l"(r) : "r"(a), "r"(b)); return r;
}
__device__ __forceinline__ float2 funpack(ull v) {
    unsigned lo, hi;
    asm("mov.b64 {%0, %1}, %2;" : "=r"(lo), "=r"(hi) : "l"(v));
    return make_float2(__uint_as_float(lo), __uint_as_float(hi));
}

// ---------------- scratch ----------------
__device__ float g_Q[TOK*HDIM];
__device__ float g_K[TOK*HDIM];
__device__ float g_V[TOK*HDIM];
__device__ float g_G[TOK*HDIM];
__device__ float g_H[TOK*HU];
__device__ float g_sigma[TOK];
__device__ float g_ctxp[BSZ*NHEAD*32*HDHD];

// =====================================================================
// Kernel 1: tiled SGEMM  out = act(x @ W + bias)   (FFMA2 + reg prefetch)
//   blockIdx.z: 0=Q 1=K 2=V 3=G(sigmoid) 4=U1(relu, N=256)
// =====================================================================
__global__ __launch_bounds__(256, 2)
void gemm_kernel(const float* __restrict__ x,
                 const float* __restrict__ Wq, const float* __restrict__ bq,
                 const float* __restrict__ Wk, const float* __restrict__ bk,
                 const float* __restrict__ Wv, const float* __restrict__ bv,
                 const float* __restrict__ Wg, const float* __restrict__ bg,
                 const float* __restrict__ Wu1, const float* __restrict__ bu1)
{
    int which = blockIdx.z;
    const float* W; const float* bias; float* out; int N;
    switch (which) {
        case 0: W = Wq;  bias = bq;  out = g_Q; N = 1024; break;
        case 1: W = Wk;  bias = bk;  out = g_K; N = 1024; break;
        case 2: W = Wv;  bias = bv;  out = g_V; N = 1024; break;
        case 3: W = Wg;  bias = bg;  out = g_G; N = 1024; break;
        default:W = Wu1; bias = bu1; out = g_H; N = 256;  break;
    }
    int n0 = blockIdx.x * 128;
    if (n0 >= N) return;
    int m0 = blockIdx.y * 128;

    __shared__ float As2[16*128*2];   // duplicated pairs: (k*128+m)*2 -> (a,a)
    __shared__ float Bs[16*128];      // Bs[k*128+n]

    int t  = threadIdx.x;
    int ty = t >> 4, tx = t & 15;

    ull acc[8][4];
    #pragma unroll
    for (int i = 0; i < 8; i++)
        #pragma unroll
        for (int j = 0; j < 4; j++) acc[i][j] = 0ull;

    int arow = t >> 2;            // 0..63 (also +64)
    int acol = (t & 3) << 2;      // 0,4,8,12
    int brow = t >> 4;            // 0..15
    int bcol = (t & 15) << 3;     // 0..120

    const float* xa0 = x + (size_t)(m0 + arow) * 1024 + acol;
    const float* xa1 = xa0 + (size_t)64 * 1024;
    const float* xw  = W + (size_t)brow * N + n0 + bcol;

    float4 a0 = *(const float4*)(xa0);
    float4 a1 = *(const float4*)(xa1);
    float4 b0 = *(const float4*)(xw);
    float4 b1 = *(const float4*)(xw + 4);

    for (int k0 = 0; k0 < 1024; k0 += 16) {
        __syncthreads();
        #pragma unroll
        for (int i = 0; i < 4; i++) {
            int k = acol + i;
            float v0 = (&a0.x)[i];
            float v1 = (&a1.x)[i];
            *(float2*)&As2[(k*128 + arow     )*2] = make_float2(v0, v0);
            *(float2*)&As2[(k*128 + arow + 64)*2] = make_float2(v1, v1);
        }
        *(float4*)&Bs[brow*128 + bcol]     = b0;
        *(float4*)&Bs[brow*128 + bcol + 4] = b1;
        __syncthreads();

        if (k0 + 16 < 1024) {
            a0 = *(const float4*)(xa0 + k0 + 16);
            a1 = *(const float4*)(xa1 + k0 + 16);
            b0 = *(const float4*)(xw + (size_t)(k0 + 16) * N);
            b1 = *(const float4*)(xw + (size_t)(k0 + 16) * N + 4);
        }

        #pragma unroll
        for (int k = 0; k < 16; k++) {
            const ulonglong2* ap = (const ulonglong2*)&As2[(k*128 + ty*8)*2];
            ulonglong2 A0 = ap[0], A1 = ap[1], A2 = ap[2], A3 = ap[3];
            const ulonglong2* bp = (const ulonglong2*)&Bs[k*128 + tx*8];
            ulonglong2 B0 = bp[0], B1 = bp[1];
            ull am[8] = {A0.x, A0.y, A1.x, A1.y, A2.x, A2.y, A3.x, A3.y};
            ull bn[4] = {B0.x, B0.y, B1.x, B1.y};
            #pragma unroll
            for (int i = 0; i < 8; i++)
                #pragma unroll
                for (int j = 0; j < 4; j++)
                    ffma2(acc[i][j], am[i], bn[j]);
        }
    }

    #pragma unroll
    for (int i = 0; i < 8; i++) {
        int row = m0 + ty*8 + i;
        float o[8];
        #pragma unroll
        for (int j = 0; j < 4; j++) {
            float2 p = funpack(acc[i][j]);
            o[2*j] = p.x; o[2*j+1] = p.y;
        }
        #pragma unroll
        for (int j = 0; j < 8; j++) {
            int col = n0 + tx*8 + j;
            float v = o[j] + bias[col];
            if (which == 3)      v = 1.0f / (1.0f + expf(-v));
            else if (which == 4) v = fmaxf(v, 0.0f);
            o[j] = v;
        }
        *(float4*)(out + (size_t)row * N + n0 + tx*8)     = make_float4(o[0],o[1],o[2],o[3]);
        *(float4*)(out + (size_t)row * N + n0 + tx*8 + 4) = make_float4(o[4],o[5],o[6],o[7]);
    }
}

// =====================================================================
// Kernel 2: sigma = softplus(H @ Wu2 + bu2) + 1e-6
// =====================================================================
__global__ void sigma_finish_kernel(const float* __restrict__ Wu2,
                                    const float* __restrict__ bu2,
                                    float* __restrict__ out_sigma)
{
    int w = threadIdx.x >> 5, lane = threadIdx.x & 31;
    int row = blockIdx.x * 8 + w;
    const float* hr = g_H + (size_t)row * HU;
    float s = 0.0f;
    #pragma unroll
    for (int c = 0; c < 8; c++) {
        int j = lane + (c << 5);
        s = fmaf(hr[j], Wu2[j], s);
    }
    #pragma unroll
    for (int o = 16; o > 0; o >>= 1) s += __shfl_xor_sync(0xffffffffu, s, o);
    if (lane == 0) {
        float u  = s + bu2[0];
        float sp = fmaxf(u, 0.0f) + log1pf(expf(-fabsf(u))) + 1e-6f;
        g_sigma[row]   = sp;
        out_sigma[row] = sp;
    }
}

// =====================================================================
// Kernel 3: attention (FFMA2 + K/V register prefetch)
// Block = (mtile 32 rows, head, batch). 256 threads.
// =====================================================================
#define ATTN_SMEM_FLOATS (32*1024 + 64*32*2 + 128*65 + 1024 + 512)

__global__ __launch_bounds__(256, 1)
void attn_kernel(float* __restrict__ attn_out)
{
    extern __shared__ float sm[];
    float* S   = sm;                    // [32][1024] scores -> probs
    float* Qs2 = S   + 32*1024;         // duplicated Q: (k*32+m)*2
    float* KVs = Qs2 + 64*32*2;         // K: [k][128] (8192) | V: [n][65] (8320)
    float* rs  = KVs + 128*65;          // 1/sigma
    float* red = rs  + 1024;            // [8][64]

    int mt = blockIdx.x, h = blockIdx.y, b = blockIdx.z;
    int m0 = mt * 32;
    int t  = threadIdx.x;

    for (int i = t; i < 1024; i += 256) rs[i] = 1.0f / g_sigma[b*1024 + i];

    {   // Q tile -> duplicated smem: Qs2[(k*32+m)*2] = (q,q)
        int m = t >> 3, part = t & 7;
        const float* qp = g_Q + ((size_t)(b*1024 + m0 + m))*1024 + h*64 + part*8;
        float4 q0 = *(const float4*)qp;
        float4 q1 = *(const float4*)(qp + 4);
        int k = part*8;
        #pragma unroll
        for (int j = 0; j < 4; j++) {
            float v0 = (&q0.x)[j], v1 = (&q1.x)[j];
            *(float2*)&Qs2[((k+j  )*32 + m)*2] = make_float2(v0, v0);
            *(float2*)&Qs2[((k+j+4)*32 + m)*2] = make_float2(v1, v1);
        }
    }
    __syncthreads();

    // ---- scores ----
    int tmS = (t >> 5) << 2;   // 0..28
    int tnS = (t & 31) << 2;   // 0..124
    int kn   = t >> 1, kpart = t & 1;                 // K loader mapping
    const float* kbase = g_K + ((size_t)(b*1024 + kn))*1024 + h*64 + kpart*32;

    float4 kreg[8];
    #pragma unroll
    for (int i = 0; i < 8; i++) kreg[i] = *(const float4*)(kbase + i*4);

    for (int nt = 0; nt < 8; nt++) {
        int n0 = nt << 7;
        __syncthreads();
        #pragma unroll
        for (int i = 0; i < 8; i++) {
            float4 kv = kreg[i];
            int kk = kpart*32 + i*4;
            KVs[(kk+0)*128 + kn] = kv.x; KVs[(kk+1)*128 + kn] = kv.y;
            KVs[(kk+2)*128 + kn] = kv.z; KVs[(kk+3)*128 + kn] = kv.w;
        }
        __syncthreads();
        if (nt < 7) {
            const float* nb = kbase + (size_t)128 * 1024;
            kbase = nb;
            #pragma unroll
            for (int i = 0; i < 8; i++) kreg[i] = *(const float4*)(nb + i*4);
        }

        ull accs[4][2];
        #pragma unroll
        for (int i = 0; i < 4; i++) { accs[i][0] = 0ull; accs[i][1] = 0ull; }

        #pragma unroll 16
        for (int k = 0; k < 64; k++) {
            const ulonglong2* ap = (const ulonglong2*)&Qs2[(k*32 + tmS)*2];
            ulonglong2 A0 = ap[0], A1 = ap[1];
            const ulonglong2* bp = (const ulonglong2*)&KVs[k*128 + tnS];
            ulonglong2 B0 = bp[0];
            ull am[4] = {A0.x, A0.y, A1.x, A1.y};
            #pragma unroll
            for (int i = 0; i < 4; i++) {
                ffma2(accs[i][0], am[i], B0.x);
                ffma2(accs[i][1], am[i], B0.y);
            }
        }
        #pragma unroll
        for (int i = 0; i < 4; i++) {
            int m = tmS + i;
            float fm = 0.125f * rs[m0 + m];
            #pragma unroll
            for (int jp = 0; jp < 2; jp++) {
                float2 p = funpack(accs[i][jp]);
                int n = tnS + 2*jp;
                *(float2*)&S[m*1024 + n0 + n] =
                    make_float2(p.x * fm * rs[n0+n], p.y * fm * rs[n0+n+1]);
            }
        }
    }
    __syncthreads();

    // ---- softmax per row; write attn; keep P in S ----
    {
        int w = t >> 5, lane = t & 31;
        float* ab = attn_out + ((size_t)((b*NHEAD + h)*1024 + m0))*1024;
        for (int r = 0; r < 4; r++) {
            int m = (w << 2) + r;
            float* Sr = S + m*1024;
            float mx = -1e30f;
            #pragma unroll
            for (int c = 0; c < 32; c++) mx = fmaxf(mx, Sr[lane + (c<<5)]);
            #pragma unroll
            for (int o = 16; o > 0; o >>= 1) mx = fmaxf(mx, __shfl_xor_sync(0xffffffffu, mx, o));
            float vals[32];
            float sum = 0.0f;
            #pragma unroll
            for (int c = 0; c < 32; c++) {
                float e = exp2f((Sr[lane + (c<<5)] - mx) * 1.4426950408889634f);
                vals[c] = e; sum += e;
            }
            #pragma unroll
            for (int o = 16; o > 0; o >>= 1) sum += __shfl_xor_sync(0xffffffffu, sum, o);
            float inv = 1.0f / sum;
            float* gr = ab + (size_t)m * 1024;
            #pragma unroll
            for (int c = 0; c < 32; c++) {
                float p = vals[c] * inv;
                Sr[lane + (c<<5)] = p;
                gr[lane + (c<<5)] = p;
            }
        }
    }
    __syncthreads();

    // ---- ctx = P @ V (FFMA2, pack along d), gate, reduce over m ----
    int d2 = t & 31;        // head-dim pair index: d = 2*d2, 2*d2+1
    int mg = t >> 5;        // 0..7, rows mg*4..mg*4+3
    ull acc2[4] = {0ull, 0ull, 0ull, 0ull};

    int vn = t & 127, vhalf = t >> 7;
    const float* vbase = g_V + ((size_t)(b*1024 + vn))*1024 + h*64 + vhalf*32;
    float4 vreg[8];
    #pragma unroll
    for (int i = 0; i < 8; i++) vreg[i] = *(const float4*)(vbase + i*4);

    for (int nt = 0; nt < 8; nt++) {
        int n0 = nt << 7;
        __syncthreads();
        {
            float* dst = KVs + vn*65 + vhalf*32;
            #pragma unroll
            for (int i = 0; i < 8; i++) {
                float4 vv = vreg[i];
                dst[i*4+0]=vv.x; dst[i*4+1]=vv.y; dst[i*4+2]=vv.z; dst[i*4+3]=vv.w;
            }
        }
        __syncthreads();
        if (nt < 7) {
            const float* nb = vbase + (size_t)128 * 1024;
            vbase = nb;
            #pragma unroll
            for (int i = 0; i < 8; i++) vreg[i] = *(const float4*)(nb + i*4);
        }

        #pragma unroll 8
        for (int n = 0; n < 128; n += 2) {
            ull v2a = fpack(KVs[(n  )*65 + 2*d2], KVs[(n  )*65 + 2*d2 + 1]);
            ull v2b = fpack(KVs[(n+1)*65 + 2*d2], KVs[(n+1)*65 + 2*d2 + 1]);
            #pragma unroll
            for (int i = 0; i < 4; i++) {
                float2 s2 = *(const float2*)&S[(mg*4 + i)*1024 + n0 + n];
                ffma2(acc2[i], fdup(s2.x), v2a);
                ffma2(acc2[i], fdup(s2.y), v2b);
            }
        }
        __syncthreads();
    }

    float p0 = 0.0f, p1 = 0.0f;
    #pragma unroll
    for (int i = 0; i < 4; i++) {
        int m = mg*4 + i;
        float2 a  = funpack(acc2[i]);
        float2 g2 = *(const float2*)&g_G[((size_t)(b*1024 + m0 + m))*1024 + h*64 + 2*d2];
        p0 = fmaf(a.x, g2.x, p0);
        p1 = fmaf(a.y, g2.y, p1);
    }
    red[mg*64 + 2*d2    ] = p0;
    red[mg*64 + 2*d2 + 1] = p1;
    __syncthreads();
    if (t < 64) {
        float s = 0.0f;
        #pragma unroll
        for (int g = 0; g < 8; g++) s += red[g*64 + t];
        g_ctxp[(((size_t)(b*NHEAD + h))*32 + mt)*64 + t] = s;
    }
}

// =====================================================================
// Kernel 4: z = mean_m(fused) @ Wo + bo   (64 blocks)
// =====================================================================
__global__ void z_kernel(const float* __restrict__ Wo, const float* __restrict__ bo,
                         float* __restrict__ z)
{
    __shared__ float mf[1024];
    int b = blockIdx.x, cb = blockIdx.y, t = threadIdx.x;   // 128 threads
    for (int j = t; j < 1024; j += 128) {
        const float* p = g_ctxp + ((size_t)(b*NHEAD + (j >> 6)))*32*64 + (j & 63);
        float s = 0.0f;
        #pragma unroll
        for (int mtl = 0; mtl < 32; mtl++) s += p[mtl*64];
        mf[j] = s * (1.0f/1024.0f);
    }
    __syncthreads();
    int c = cb*128 + t;
    float acc = bo[c];
    #pragma unroll 8
    for (int j = 0; j < 1024; j++) acc = fmaf(mf[j], Wo[j*1024 + c], acc);
    z[(size_t)b*1024 + c] = acc;
}

// =====================================================================
// launch
// =====================================================================
extern "C" void kernel_launch(void* const* d_in, const int* in_sizes, int n_in,
                              void* d_out, int out_size)
{
    const float* x   = (const float*)d_in[0];
    const float* Wq  = (const float*)d_in[1];  const float* bq  = (const float*)d_in[2];
    const float* Wk  = (const float*)d_in[3];  const float* bk  = (const float*)d_in[4];
    const float* Wv  = (const float*)d_in[5];  const float* bv  = (const float*)d_in[6];
    const float* Wg  = (const float*)d_in[7];  const float* bg  = (const float*)d_in[8];
    const float* Wo  = (const float*)d_in[9];  const float* bo  = (const float*)d_in[10];
    const float* Wu1 = (const float*)d_in[11]; const float* bu1 = (const float*)d_in[12];
    const float* Wu2 = (const float*)d_in[13]; const float* bu2 = (const float*)d_in[14];

    float* out       = (float*)d_out;
    float* z_out     = out;                                        // [8,1024]
    float* attn_out  = out + 8192;                                 // [8,16,1024,1024]
    float* sigma_out = out + 8192 + (size_t)BSZ*NHEAD*MSEQ*MSEQ;   // [8,1024]

    cudaFuncSetAttribute(attn_kernel, cudaFuncAttributeMaxDynamicSharedMemorySize,
                         ATTN_SMEM_FLOATS * (int)sizeof(float));

    gemm_kernel<<<dim3(8, 64, 5), 256>>>(x, Wq, bq, Wk, bk, Wv, bv, Wg, bg, Wu1, bu1);
    sigma_finish_kernel<<<TOK / 8, 256>>>(Wu2, bu2, sigma_out);
    attn_kernel<<<dim3(32, NHEAD, BSZ), 256, ATTN_SMEM_FLOATS * (int)sizeof(float)>>>(attn_out);
    z_kernel<<<dim3(BSZ, 8), 128>>>(Wo, bo, z_out);
}

// round 8
// speedup vs baseline: 1.1198x; 1.1198x over previous
#include <cuda_runtime.h>
#include <math.h>

// ---------------- problem constants ----------------
#define BSZ   8
#define MSEQ  1024
#define HDIM  1024
#define NHEAD 16
#define HDHD  64
#define HU    256
#define TOK   (BSZ*MSEQ)          // 8192

typedef unsigned long long ull;

// ---- packed fp32x2 helpers (sm_103a FFMA2 path) ----
__device__ __forceinline__ void ffma2(ull &d, ull a, ull b) {
    asm("fma.rn.f32x2 %0, %1, %2, %0;" : "+l"(d) : "l"(a), "l"(b));
}
__device__ __forceinline__ ull fdup(float x) {
    ull r; unsigned u = __float_as_uint(x);
    asm("mov.b64 %0, {%1, %1};" : "=l"(r) : "r"(u)); return r;
}
__device__ __forceinline__ float2 funpack(ull v) {
    unsigned lo, hi;
    asm("mov.b64 {%0, %1}, %2;" : "=r"(lo), "=r"(hi) : "l"(v));
    return make_float2(__uint_as_float(lo), __uint_as_float(hi));
}

// ---------------- scratch ----------------
__device__ float g_Q[TOK*HDIM];
__device__ float g_K[TOK*HDIM];
__device__ float g_V[TOK*HDIM];
__device__ float g_G[TOK*HDIM];
__device__ float g_H[TOK*HU];
__device__ float g_sigma[TOK];
__device__ float g_ctxp[BSZ*NHEAD*32*HDHD];

// =====================================================================
// Kernel 1: tiled SGEMM  out = act(x @ W + bias)
// plain smem (no dup), A duplicated in regs via mov.b64; FFMA2 on n-pairs
// per k: 64B smem <-> 32 FFMA2  (balanced 16:16 cyc)
// =====================================================================
__global__ __launch_bounds__(256, 2)
void gemm_kernel(const float* __restrict__ x,
                 const float* __restrict__ Wq, const float* __restrict__ bq,
                 const float* __restrict__ Wk, const float* __restrict__ bk,
                 const float* __restrict__ Wv, const float* __restrict__ bv,
                 const float* __restrict__ Wg, const float* __restrict__ bg,
                 const float* __restrict__ Wu1, const float* __restrict__ bu1)
{
    int which = blockIdx.z;
    const float* W; const float* bias; float* out; int N;
    switch (which) {
        case 0: W = Wq;  bias = bq;  out = g_Q; N = 1024; break;
        case 1: W = Wk;  bias = bk;  out = g_K; N = 1024; break;
        case 2: W = Wv;  bias = bv;  out = g_V; N = 1024; break;
        case 3: W = Wg;  bias = bg;  out = g_G; N = 1024; break;
        default:W = Wu1; bias = bu1; out = g_H; N = 256;  break;
    }
    int n0 = blockIdx.x * 128;
    if (n0 >= N) return;
    int m0 = blockIdx.y * 128;

    __shared__ __align__(16) float As[16][128];   // As[k][m]
    __shared__ __align__(16) float Bs[16][128];   // Bs[k][n]

    int t  = threadIdx.x;
    int ty = t >> 4, tx = t & 15;

    ull acc[8][4];
    #pragma unroll
    for (int i = 0; i < 8; i++)
        #pragma unroll
        for (int j = 0; j < 4; j++) acc[i][j] = 0ull;

    int arow = t >> 2;            // 0..63 (also +64)
    int acol = (t & 3) << 2;      // 0,4,8,12
    int brow = t >> 4;            // 0..15
    int bcol = (t & 15) << 3;     // 0..120

    const float* xa0 = x + (size_t)(m0 + arow) * 1024 + acol;
    const float* xa1 = xa0 + (size_t)64 * 1024;
    const float* xw  = W + (size_t)brow * N + n0 + bcol;

    float4 a0 = *(const float4*)(xa0);
    float4 a1 = *(const float4*)(xa1);
    float4 b0 = *(const float4*)(xw);
    float4 b1 = *(const float4*)(xw + 4);

    for (int k0 = 0; k0 < 1024; k0 += 16) {
        __syncthreads();
        As[acol + 0][arow] = a0.x; As[acol + 1][arow] = a0.y;
        As[acol + 2][arow] = a0.z; As[acol + 3][arow] = a0.w;
        As[acol + 0][arow + 64] = a1.x; As[acol + 1][arow + 64] = a1.y;
        As[acol + 2][arow + 64] = a1.z; As[acol + 3][arow + 64] = a1.w;
        *(float4*)&Bs[brow][bcol]     = b0;
        *(float4*)&Bs[brow][bcol + 4] = b1;
        __syncthreads();

        if (k0 + 16 < 1024) {
            a0 = *(const float4*)(xa0 + k0 + 16);
            a1 = *(const float4*)(xa1 + k0 + 16);
            b0 = *(const float4*)(xw + (size_t)(k0 + 16) * N);
            b1 = *(const float4*)(xw + (size_t)(k0 + 16) * N + 4);
        }

        #pragma unroll
        for (int k = 0; k < 16; k++) {
            float4 av0 = *(const float4*)&As[k][ty * 8];
            float4 av1 = *(const float4*)&As[k][ty * 8 + 4];
            const ulonglong2* bp = (const ulonglong2*)&Bs[k][tx * 8];
            ulonglong2 B0 = bp[0], B1 = bp[1];
            ull bn[4] = {B0.x, B0.y, B1.x, B1.y};
            ull am[8] = {fdup(av0.x), fdup(av0.y), fdup(av0.z), fdup(av0.w),
                         fdup(av1.x), fdup(av1.y), fdup(av1.z), fdup(av1.w)};
            #pragma unroll
            for (int i = 0; i < 8; i++)
                #pragma unroll
                for (int j = 0; j < 4; j++)
                    ffma2(acc[i][j], am[i], bn[j]);
        }
    }

    #pragma unroll
    for (int i = 0; i < 8; i++) {
        int row = m0 + ty*8 + i;
        float o[8];
        #pragma unroll
        for (int j = 0; j < 4; j++) {
            float2 p = funpack(acc[i][j]);
            o[2*j] = p.x; o[2*j+1] = p.y;
        }
        #pragma unroll
        for (int j = 0; j < 8; j++) {
            int col = n0 + tx*8 + j;
            float v = o[j] + bias[col];
            if (which == 3)      v = 1.0f / (1.0f + expf(-v));
            else if (which == 4) v = fmaxf(v, 0.0f);
            o[j] = v;
        }
        *(float4*)(out + (size_t)row * N + n0 + tx*8)     = make_float4(o[0],o[1],o[2],o[3]);
        *(float4*)(out + (size_t)row * N + n0 + tx*8 + 4) = make_float4(o[4],o[5],o[6],o[7]);
    }
}

// =====================================================================
// Kernel 2: sigma = softplus(H @ Wu2 + bu2) + 1e-6
// =====================================================================
__global__ void sigma_finish_kernel(const float* __restrict__ Wu2,
                                    const float* __restrict__ bu2,
                                    float* __restrict__ out_sigma)
{
    int w = threadIdx.x >> 5, lane = threadIdx.x & 31;
    int row = blockIdx.x * 8 + w;
    const float* hr = g_H + (size_t)row * HU;
    float s = 0.0f;
    #pragma unroll
    for (int c = 0; c < 8; c++) {
        int j = lane + (c << 5);
        s = fmaf(hr[j], Wu2[j], s);
    }
    #pragma unroll
    for (int o = 16; o > 0; o >>= 1) s += __shfl_xor_sync(0xffffffffu, s, o);
    if (lane == 0) {
        float u  = s + bu2[0];
        float sp = fmaxf(u, 0.0f) + log1pf(expf(-fabsf(u))) + 1e-6f;
        g_sigma[row]   = sp;
        out_sigma[row] = sp;
    }
}

// =====================================================================
// Kernel 3: attention. Block = (32-row mtile, head, batch), 256 threads.
// Scores: n-tiles of 256, microtile 4m x 8n (FFMA2 on n-pairs).
// PV: n-tiles of 128, 4-way n-split, microtile 8m x 4d (FFMA2 on d-pairs).
// =====================================================================
#define ATTN_SMEM_FLOATS (32*1024 + 64*32 + 16384 + 1024 + 256)

__global__ __launch_bounds__(256, 1)
void attn_kernel(float* __restrict__ attn_out)
{
    extern __shared__ float sm[];
    float* S   = sm;                  // [32][1024] scores -> probs ; later: ctx scratch
    float* Qs  = S   + 32*1024;       // [k][m] 64x32
    float* KV  = Qs  + 64*32;         // K: [k][256] (16384) | V: [n][68] (8704)
    float* rs  = KV  + 16384;         // 1/sigma (1024)
    float* red = rs  + 1024;          // [4][64]

    int mt = blockIdx.x, h = blockIdx.y, b = blockIdx.z;
    int m0 = mt * 32;
    int t  = threadIdx.x;

    for (int i = t; i < 1024; i += 256) rs[i] = 1.0f / g_sigma[b*1024 + i];

    {   // Q tile transposed: Qs[k][m]
        int m = t >> 3, part = t & 7;
        const float* qp = g_Q + ((size_t)(b*1024 + m0 + m))*1024 + h*64 + part*8;
        float4 q0 = *(const float4*)qp;
        float4 q1 = *(const float4*)(qp + 4);
        int k = part*8;
        Qs[(k+0)*32+m]=q0.x; Qs[(k+1)*32+m]=q0.y; Qs[(k+2)*32+m]=q0.z; Qs[(k+3)*32+m]=q0.w;
        Qs[(k+4)*32+m]=q1.x; Qs[(k+5)*32+m]=q1.y; Qs[(k+6)*32+m]=q1.z; Qs[(k+7)*32+m]=q1.w;
    }

    // ---- scores: 4 n-tiles of 256 ----
    int tm4 = (t >> 5) << 2;    // 0..28  (warp-uniform -> A broadcast)
    int tn8 = (t & 31) << 3;    // 0..248
    for (int nt = 0; nt < 4; nt++) {
        int n0 = nt << 8;
        __syncthreads();
        #pragma unroll
        for (int p = 0; p < 2; p++) {   // K tile transposed: KV[k][256]
            int n = p*128 + (t >> 1), half = t & 1;
            const float* kp = g_K + ((size_t)(b*1024 + n0 + n))*1024 + h*64 + half*32;
            #pragma unroll
            for (int i = 0; i < 8; i++) {
                float4 kv = *(const float4*)(kp + i*4);
                int kk = half*32 + i*4;
                KV[(kk+0)*256+n]=kv.x; KV[(kk+1)*256+n]=kv.y;
                KV[(kk+2)*256+n]=kv.z; KV[(kk+3)*256+n]=kv.w;
            }
        }
        __syncthreads();

        ull acc[4][4];   // 4 m x 4 n-pairs
        #pragma unroll
        for (int i = 0; i < 4; i++)
            #pragma unroll
            for (int j = 0; j < 4; j++) acc[i][j] = 0ull;

        #pragma unroll 8
        for (int k = 0; k < 64; k++) {
            float4 av = *(const float4*)&Qs[k*32 + tm4];
            const ulonglong2* bp = (const ulonglong2*)&KV[k*256 + tn8];
            ulonglong2 B0 = bp[0], B1 = bp[1];
            ull bn[4] = {B0.x, B0.y, B1.x, B1.y};
            ull am[4] = {fdup(av.x), fdup(av.y), fdup(av.z), fdup(av.w)};
            #pragma unroll
            for (int i = 0; i < 4; i++)
                #pragma unroll
                for (int j = 0; j < 4; j++)
                    ffma2(acc[i][j], am[i], bn[j]);
        }
        #pragma unroll
        for (int i = 0; i < 4; i++) {
            int m = tm4 + i;
            float fm = 0.125f * rs[m0 + m];
            float o[8];
            #pragma unroll
            for (int j = 0; j < 4; j++) {
                float2 p = funpack(acc[i][j]);
                o[2*j]   = p.x * fm * rs[n0 + tn8 + 2*j];
                o[2*j+1] = p.y * fm * rs[n0 + tn8 + 2*j + 1];
            }
            *(float4*)&S[m*1024 + n0 + tn8]     = make_float4(o[0],o[1],o[2],o[3]);
            *(float4*)&S[m*1024 + n0 + tn8 + 4] = make_float4(o[4],o[5],o[6],o[7]);
        }
    }
    __syncthreads();

    // ---- softmax per row; write attn; keep P in S ----
    {
        int w = t >> 5, lane = t & 31;
        float* ab = attn_out + ((size_t)((b*NHEAD + h)*1024 + m0))*1024;
        for (int r = 0; r < 4; r++) {
            int m = (w << 2) + r;
            float* Sr = S + m*1024;
            float mx = -1e30f;
            #pragma unroll
            for (int c = 0; c < 32; c++) mx = fmaxf(mx, Sr[lane + (c<<5)]);
            #pragma unroll
            for (int o = 16; o > 0; o >>= 1) mx = fmaxf(mx, __shfl_xor_sync(0xffffffffu, mx, o));
            float vals[32];
            float sum = 0.0f;
            #pragma unroll
            for (int c = 0; c < 32; c++) {
                float e = exp2f((Sr[lane + (c<<5)] - mx) * 1.4426950408889634f);
                vals[c] = e; sum += e;
            }
            #pragma unroll
            for (int o = 16; o > 0; o >>= 1) sum += __shfl_xor_sync(0xffffffffu, sum, o);
            float inv = 1.0f / sum;
            float* gr = ab + (size_t)m * 1024;
            #pragma unroll
            for (int c = 0; c < 32; c++) {
                float p = vals[c] * inv;
                Sr[lane + (c<<5)] = p;
                gr[lane + (c<<5)] = p;
            }
        }
    }
    __syncthreads();

    // ---- ctx = P @ V : 8 n-tiles of 128, 4-way n-split ----
    int sub = t >> 6;           // n quarter within tile
    int u   = t & 63;
    int dp4 = (u & 15) << 2;    // d block of 4 (2 pairs)
    int mg8 = (u >> 4) << 3;    // m block of 8
    ull acc2[8][2];
    #pragma unroll
    for (int i = 0; i < 8; i++) { acc2[i][0] = 0ull; acc2[i][1] = 0ull; }

    int vn = t & 127, vhalf = t >> 7;
    const float* vbase = g_V + ((size_t)(b*1024 + vn))*1024 + h*64 + vhalf*32;
    float4 vreg[8];
    #pragma unroll
    for (int i = 0; i < 8; i++) vreg[i] = *(const float4*)(vbase + i*4);

    for (int nt = 0; nt < 8; nt++) {
        int n0 = nt << 7;
        __syncthreads();
        {   // V tile: KV[n*68 + d], pad 68 -> conflict-free float4 access
            float* dst = KV + vn*68 + vhalf*32;
            #pragma unroll
            for (int i = 0; i < 8; i++) *(float4*)&dst[i*4] = vreg[i];
        }
        __syncthreads();
        if (nt < 7) {
            vbase += (size_t)128 * 1024;
            #pragma unroll
            for (int i = 0; i < 8; i++) vreg[i] = *(const float4*)(vbase + i*4);
        }

        #pragma unroll 4
        for (int nn = 0; nn < 32; nn++) {
            int n = sub*32 + nn;
            const ulonglong2* vp = (const ulonglong2*)&KV[n*68 + dp4];
            ulonglong2 V0 = vp[0];              // 2 d-pairs
            #pragma unroll
            for (int i = 0; i < 8; i++) {
                ull sd = fdup(S[(mg8 + i)*1024 + n0 + n]);
                ffma2(acc2[i][0], sd, V0.x);
                ffma2(acc2[i][1], sd, V0.y);
            }
        }
    }
    __syncthreads();   // PV done reading S -> reuse S as ctx scratch

    {   // scr[sub][m][d]
        float* scr = S;
        #pragma unroll
        for (int i = 0; i < 8; i++) {
            float2 p0 = funpack(acc2[i][0]);
            float2 p1 = funpack(acc2[i][1]);
            *(float4*)&scr[sub*2048 + (mg8 + i)*64 + dp4] = make_float4(p0.x, p0.y, p1.x, p1.y);
        }
    }
    __syncthreads();
    {   // gate + reduce over m
        float* scr = S;
        int d = t & 63, mgr = t >> 6;
        float part = 0.0f;
        #pragma unroll
        for (int i = 0; i < 8; i++) {
            int m = mgr*8 + i;
            float c = scr[m*64 + d] + scr[2048 + m*64 + d]
                    + scr[4096 + m*64 + d] + scr[6144 + m*64 + d];
            float gv = g_G[((size_t)(b*1024 + m0 + m))*1024 + h*64 + d];
            part = fmaf(c, gv, part);
        }
        red[t] = part;
    }
    __syncthreads();
    if (t < 64) {
        float s = red[t] + red[64 + t] + red[128 + t] + red[192 + t];
        g_ctxp[(((size_t)(b*NHEAD + h))*32 + mt)*64 + t] = s;
    }
}

// =====================================================================
// Kernel 4: z = mean_m(fused) @ Wo + bo   (grid 8x4, 256 thr)
// =====================================================================
__global__ void z_kernel(const float* __restrict__ Wo, const float* __restrict__ bo,
                         float* __restrict__ z)
{
    __shared__ float mf[1024];
    int b = blockIdx.x, cb = blockIdx.y, t = threadIdx.x;
    for (int j = t; j < 1024; j += 256) {
        const float* p = g_ctxp + ((size_t)(b*NHEAD + (j >> 6)))*32*64 + (j & 63);
        float s = 0.0f;
        #pragma unroll
        for (int mtl = 0; mtl < 32; mtl++) s += p[mtl*64];
        mf[j] = s * (1.0f/1024.0f);
    }
    __syncthreads();
    int c = cb*256 + t;
    float a0 = 0.f, a1 = 0.f, a2 = 0.f, a3 = 0.f;
    #pragma unroll 4
    for (int j = 0; j < 1024; j += 4) {
        a0 = fmaf(mf[j  ], Wo[(j  )*1024 + c], a0);
        a1 = fmaf(mf[j+1], Wo[(j+1)*1024 + c], a1);
        a2 = fmaf(mf[j+2], Wo[(j+2)*1024 + c], a2);
        a3 = fmaf(mf[j+3], Wo[(j+3)*1024 + c], a3);
    }
    z[(size_t)b*1024 + c] = (a0 + a1) + (a2 + a3) + bo[c];
}

// =====================================================================
// launch
// =====================================================================
extern "C" void kernel_launch(void* const* d_in, const int* in_sizes, int n_in,
                              void* d_out, int out_size)
{
    const float* x   = (const float*)d_in[0];
    const float* Wq  = (const float*)d_in[1];  const float* bq  = (const float*)d_in[2];
    const float* Wk  = (const float*)d_in[3];  const float* bk  = (const float*)d_in[4];
    const float* Wv  = (const float*)d_in[5];  const float* bv  = (const float*)d_in[6];
    const float* Wg  = (const float*)d_in[7];  const float* bg  = (const float*)d_in[8];
    const float* Wo  = (const float*)d_in[9];  const float* bo  = (const float*)d_in[10];
    const float* Wu1 = (const float*)d_in[11]; const float* bu1 = (const float*)d_in[12];
    const float* Wu2 = (const float*)d_in[13]; const float* bu2 = (const float*)d_in[14];

    float* out       = (float*)d_out;
    float* z_out     = out;                                        // [8,1024]
    float* attn_out  = out + 8192;                                 // [8,16,1024,1024]
    float* sigma_out = out + 8192 + (size_t)BSZ*NHEAD*MSEQ*MSEQ;   // [8,1024]

    cudaFuncSetAttribute(attn_kernel, cudaFuncAttributeMaxDynamicSharedMemorySize,
                         ATTN_SMEM_FLOATS * (int)sizeof(float));

    gemm_kernel<<<dim3(8, 64, 5), 256>>>(x, Wq, bq, Wk, bk, Wv, bv, Wg, bg, Wu1, bu1);
    sigma_finish_kernel<<<TOK / 8, 256>>>(Wu2, bu2, sigma_out);
    attn_kernel<<<dim3(32, NHEAD, BSZ), 256, ATTN_SMEM_FLOATS * (int)sizeof(float)>>>(attn_out);
    z_kernel<<<dim3(BSZ, 4), 256>>>(Wo, bo, z_out);
}

// round 10
// speedup vs baseline: 1.4637x; 1.3071x over previous
#include <cuda_runtime.h>
#include <cuda_bf16.h>
#include <math.h>

// ---------------- problem constants ----------------
#define BSZ   8
#define MSEQ  1024
#define HDIM  1024
#define NHEAD 16
#define HDHD  64
#define HU    256
#define TOK   (BSZ*MSEQ)          // 8192
#define K3    3072                // 3*1024 interleaved split-K
#define NCH   48                  // K3/64 chunks

typedef unsigned long long ull;

// ---- packed fp32x2 helpers (attention kernel) ----
__device__ __forceinline__ void ffma2(ull &d, ull a, ull b) {
    asm("fma.rn.f32x2 %0, %1, %2, %0;" : "+l"(d) : "l"(a), "l"(b));
}
__device__ __forceinline__ ull fdup(float x) {
    ull r; unsigned u = __float_as_uint(x);
    asm("mov.b64 %0, {%1, %1};" : "=l"(r) : "r"(u)); return r;
}
__device__ __forceinline__ float2 funpack(ull v) {
    unsigned lo, hi;
    asm("mov.b64 {%0, %1}, %2;" : "=r"(lo), "=r"(hi) : "l"(v));
    return make_float2(__uint_as_float(lo), __uint_as_float(hi));
}

__device__ __forceinline__ unsigned smem_u32(const void* p) {
    unsigned a;
    asm("{ .reg .u64 t; cvta.to.shared.u64 t, %1; cvt.u32.u64 %0, t; }" : "=r"(a) : "l"(p));
    return a;
}
__device__ __forceinline__ void ldmx4(unsigned* r, unsigned addr) {
    asm volatile("ldmatrix.sync.aligned.m8n8.x4.shared.b16 {%0,%1,%2,%3}, [%4];"
        : "=r"(r[0]), "=r"(r[1]), "=r"(r[2]), "=r"(r[3]) : "r"(addr));
}
__device__ __forceinline__ void mma16816(float* d, const unsigned* a, const unsigned* b) {
    asm volatile("mma.sync.aligned.m16n8k16.row.col.f32.bf16.bf16.f32 "
        "{%0,%1,%2,%3}, {%4,%5,%6,%7}, {%8,%9}, {%0,%1,%2,%3};"
        : "+f"(d[0]), "+f"(d[1]), "+f"(d[2]), "+f"(d[3])
        : "r"(a[0]), "r"(a[1]), "r"(a[2]), "r"(a[3]), "r"(b[0]), "r"(b[1]));
}
__device__ __forceinline__ unsigned sw128(unsigned off) {
    return off ^ ((off >> 3) & 0x70);
}

// ---------------- scratch ----------------
__device__ float g_Q[TOK*HDIM];
__device__ float g_K[TOK*HDIM];
__device__ float g_V[TOK*HDIM];
__device__ float g_G[TOK*HDIM];
__device__ float g_H[TOK*HU];
__device__ float g_sigma[TOK];
__device__ float g_ctxp[BSZ*NHEAD*32*HDHD];
__device__ __nv_bfloat16 g_x3[(size_t)TOK*K3];             // (hi,hi,lo) interleaved
__device__ __nv_bfloat16 g_Wt3[(size_t)(4*1024+256)*K3];   // [which][n][3k] = (hi,lo,hi)

// =====================================================================
// Pre-pass 1: x -> x3 interleaved bf16 split (hi,hi,lo)
// =====================================================================
__global__ void split_x_kernel(const float* __restrict__ x)
{
    unsigned idx = blockIdx.x * 256 + threadIdx.x;
    size_t f0 = (size_t)idx * 8;
    unsigned row = (unsigned)(f0 >> 10), col = (unsigned)(f0 & 1023);
    float4 a = *(const float4*)(x + f0);
    float4 b = *(const float4*)(x + f0 + 4);
    union { __nv_bfloat16 h[24]; uint4 v[3]; } u;
    float e[8] = {a.x,a.y,a.z,a.w,b.x,b.y,b.z,b.w};
    #pragma unroll
    for (int i = 0; i < 8; i++) {
        __nv_bfloat16 hi = __float2bfloat16(e[i]);
        __nv_bfloat16 lo = __float2bfloat16(e[i] - __bfloat162float(hi));
        u.h[3*i] = hi; u.h[3*i+1] = hi; u.h[3*i+2] = lo;
    }
    __nv_bfloat16* out = g_x3 + (size_t)row * K3 + 3*col;
    uint4* o4 = (uint4*)out;
    o4[0] = u.v[0]; o4[1] = u.v[1]; o4[2] = u.v[2];
}

// =====================================================================
// Pre-pass 2: W[k][n] -> Wt3[n][3k] transposed split (hi,lo,hi)
// =====================================================================
__global__ void split_w_kernel(const float* __restrict__ Wq, const float* __restrict__ Wk,
                               const float* __restrict__ Wv, const float* __restrict__ Wg,
                               const float* __restrict__ Wu1)
{
    int which = blockIdx.z;
    const float* W; int NOUT;
    switch (which) {
        case 0: W = Wq;  NOUT = 1024; break;
        case 1: W = Wk;  NOUT = 1024; break;
        case 2: W = Wv;  NOUT = 1024; break;
        case 3: W = Wg;  NOUT = 1024; break;
        default:W = Wu1; NOUT = 256;  break;
    }
    int n0 = blockIdx.y * 32;
    if (n0 >= NOUT) return;
    int k0 = blockIdx.x * 64;
    int t = threadIdx.x;

    __shared__ float tile[64][33];
    int j = t & 31, ki0 = t >> 5;
    #pragma unroll
    for (int r = 0; r < 8; r++) {
        int k = ki0 + r*8;
        tile[k][j] = W[(size_t)(k0 + k) * NOUT + n0 + j];
    }
    __syncthreads();

    int n = t >> 3, kseg = t & 7;
    union { __nv_bfloat16 h[24]; uint4 v[3]; } u;
    #pragma unroll
    for (int e = 0; e < 8; e++) {
        float w = tile[kseg*8 + e][n];
        __nv_bfloat16 hi = __float2bfloat16(w);
        __nv_bfloat16 lo = __float2bfloat16(w - __bfloat162float(hi));
        u.h[3*e] = hi; u.h[3*e+1] = lo; u.h[3*e+2] = hi;
    }
    __nv_bfloat16* out = g_Wt3 + (size_t)which * 1024 * K3
                       + (size_t)(n0 + n) * K3 + 3*(k0 + kseg*8);
    uint4* o4 = (uint4*)out;
    o4[0] = u.v[0]; o4[1] = u.v[1]; o4[2] = u.v[2];
}

// =====================================================================
// Kernel 1: HMMA bf16 GEMM (mma.sync m16n8k16), block tile 128x128, K3=3072
// 8 warps, warp tile 32m x 64n; K-chunk 64; double-buffered SW128 smem.
// =====================================================================
#define GSM_A0 0
#define GSM_A1 16384
#define GSM_B0 32768
#define GSM_B1 49152
#define GSM_TOTAL 65536

__global__ __launch_bounds__(256, 1)
void mma_gemm_kernel(const float* __restrict__ bq, const float* __restrict__ bk,
                     const float* __restrict__ bv, const float* __restrict__ bg,
                     const float* __restrict__ bu1)
{
    int which = blockIdx.z;
    const float* bias; float* out; int NOUT;
    switch (which) {
        case 0: bias = bq;  out = g_Q; NOUT = 1024; break;
        case 1: bias = bk;  out = g_K; NOUT = 1024; break;
        case 2: bias = bv;  out = g_V; NOUT = 1024; break;
        case 3: bias = bg;  out = g_G; NOUT = 1024; break;
        default:bias = bu1; out = g_H; NOUT = 256;  break;
    }
    int n0 = blockIdx.x * 128;
    if (n0 >= NOUT) return;
    int m0 = blockIdx.y * 128;

    extern __shared__ char smem[];
    unsigned sbase = smem_u32(smem);
    int t = threadIdx.x, wid = t >> 5, lane = t & 31;
    int wm = wid & 3, wn = wid >> 2;

    // gmem loader mapping: 4 A rows + 4 B rows of 16B segs per thread per chunk
    int lrow = t >> 3, lseg = t & 7;
    const __nv_bfloat16* abase = g_x3 + (size_t)(m0 + lrow) * K3 + lseg*8;
    const __nv_bfloat16* bbase = g_Wt3 + (size_t)which * 1024 * K3
                               + (size_t)(n0 + lrow) * K3 + lseg*8;
    unsigned sts_off = sw128(lrow*128 + lseg*16);   // same for each 32-row group step of 4096B

    // ldmatrix lane address precompute (row-dependent part)
    // A frags f=0,1: row = wm*32 + f*16 + (lane&15), khalf = lane>>4
    unsigned a_rb[2], a_xm[2];
    #pragma unroll
    for (int f = 0; f < 2; f++) {
        unsigned row = wm*32 + f*16 + (lane & 15);
        a_rb[f] = row * 128;
        a_xm[f] = (row & 7) << 4;
    }
    unsigned a_kh = (lane >> 4) * 16;
    // B frag pairs p=0..3: row = wn*64 + p*16 + ((lane>>4)<<3) + (lane&7), khalf=(lane>>3)&1
    unsigned b_rb[4], b_xm[4];
    #pragma unroll
    for (int p = 0; p < 4; p++) {
        unsigned row = wn*64 + p*16 + ((lane >> 4) << 3) + (lane & 7);
        b_rb[p] = row * 128;
        b_xm[p] = (row & 7) << 4;
    }
    unsigned b_kh = ((lane >> 3) & 1) * 16;

    float acc[2][8][4];
    #pragma unroll
    for (int f = 0; f < 2; f++)
        #pragma unroll
        for (int j = 0; j < 8; j++)
            #pragma unroll
            for (int q = 0; q < 4; q++) acc[f][j][q] = 0.0f;

    unsigned abuf[2] = {sbase + GSM_A0, sbase + GSM_A1};
    unsigned bbuf[2] = {sbase + GSM_B0, sbase + GSM_B1};

    uint4 av[4], bv4[4];
    #pragma unroll
    for (int i = 0; i < 4; i++) {
        av[i]  = *(const uint4*)(abase + (size_t)i*32*K3);
        bv4[i] = *(const uint4*)(bbase + (size_t)i*32*K3);
    }

    for (int c = 0; c < NCH; c++) {
        int buf = c & 1;
        char* A = smem + (GSM_A0 + buf*16384);
        char* B = smem + (GSM_B0 - GSM_B0 + 0);   // placeholder to keep A/B symmetric
        (void)B;
        #pragma unroll
        for (int i = 0; i < 4; i++) {
            *(uint4*)(smem + (buf ? GSM_A1 : GSM_A0) + i*4096 + sts_off) = av[i];
            *(uint4*)(smem + (buf ? GSM_B1 : GSM_B0) + i*4096 + sts_off) = bv4[i];
        }
        __syncthreads();

        if (c + 1 < NCH) {
            const __nv_bfloat16* ap = abase + (c+1)*64;
            const __nv_bfloat16* bp = bbase + (c+1)*64;
            #pragma unroll
            for (int i = 0; i < 4; i++) {
                av[i]  = *(const uint4*)(ap + (size_t)i*32*K3);
                bv4[i] = *(const uint4*)(bp + (size_t)i*32*K3);
            }
        }

        unsigned Ab = abuf[buf], Bb = bbuf[buf];
        #pragma unroll
        for (int kk = 0; kk < 4; kk++) {
            unsigned kb = kk * 32;
            unsigned afr[2][4];
            #pragma unroll
            for (int f = 0; f < 2; f++)
                ldmx4(afr[f], Ab + a_rb[f] + (((kb + a_kh) ^ a_xm[f])));
            #pragma unroll
            for (int p = 0; p < 4; p++) {
                unsigned bfr[4];
                ldmx4(bfr, Bb + b_rb[p] + (((kb + b_kh) ^ b_xm[p])));
                mma16816(acc[0][2*p],   afr[0], bfr);
                mma16816(acc[0][2*p+1], afr[0], bfr + 2);
                mma16816(acc[1][2*p],   afr[1], bfr);
                mma16816(acc[1][2*p+1], afr[1], bfr + 2);
            }
        }
        __syncthreads();
    }

    // epilogue: bias + activation, write fp32
    int mrow = lane >> 2;
    int ncol = (lane & 3) * 2;
    #pragma unroll
    for (int f = 0; f < 2; f++) {
        int mA = m0 + wm*32 + f*16 + mrow;
        #pragma unroll
        for (int j = 0; j < 8; j++) {
            int n = n0 + wn*64 + j*8 + ncol;
            float bb0 = bias[n], bb1 = bias[n+1];
            float v0 = acc[f][j][0] + bb0, v1 = acc[f][j][1] + bb1;
            float v2 = acc[f][j][2] + bb0, v3 = acc[f][j][3] + bb1;
            if (which == 3) {
                v0 = 1.0f/(1.0f+expf(-v0)); v1 = 1.0f/(1.0f+expf(-v1));
                v2 = 1.0f/(1.0f+expf(-v2)); v3 = 1.0f/(1.0f+expf(-v3));
            } else if (which == 4) {
                v0 = fmaxf(v0,0.f); v1 = fmaxf(v1,0.f);
                v2 = fmaxf(v2,0.f); v3 = fmaxf(v3,0.f);
            }
            *(float2*)(out + (size_t)mA * NOUT + n)       = make_float2(v0, v1);
            *(float2*)(out + (size_t)(mA+8) * NOUT + n)   = make_float2(v2, v3);
        }
    }
}

// =====================================================================
// Kernel 2: sigma = softplus(H @ Wu2 + bu2) + 1e-6
// =====================================================================
__global__ void sigma_finish_kernel(const float* __restrict__ Wu2,
                                    const float* __restrict__ bu2,
                                    float* __restrict__ out_sigma)
{
    int w = threadIdx.x >> 5, lane = threadIdx.x & 31;
    int row = blockIdx.x * 8 + w;
    const float* hr = g_H + (size_t)row * HU;
    float s = 0.0f;
    #pragma unroll
    for (int c = 0; c < 8; c++) {
        int j = lane + (c << 5);
        s = fmaf(hr[j], Wu2[j], s);
    }
    #pragma unroll
    for (int o = 16; o > 0; o >>= 1) s += __shfl_xor_sync(0xffffffffu, s, o);
    if (lane == 0) {
        float u  = s + bu2[0];
        float sp = fmaxf(u, 0.0f) + log1pf(expf(-fabsf(u))) + 1e-6f;
        g_sigma[row]   = sp;
        out_sigma[row] = sp;
    }
}

// =====================================================================
// Kernel 3: attention (R8 passing version, unchanged)
// =====================================================================
#define ATTN_SMEM_FLOATS (32*1024 + 64*32 + 16384 + 1024 + 256)

__global__ __launch_bounds__(256, 1)
void attn_kernel(float* __restrict__ attn_out)
{
    extern __shared__ float sm[];
    float* S   = sm;
    float* Qs  = S   + 32*1024;
    float* KV  = Qs  + 64*32;
    float* rs  = KV  + 16384;
    float* red = rs  + 1024;

    int mt = blockIdx.x, h = blockIdx.y, b = blockIdx.z;
    int m0 = mt * 32;
    int t  = threadIdx.x;

    for (int i = t; i < 1024; i += 256) rs[i] = 1.0f / g_sigma[b*1024 + i];

    {
        int m = t >> 3, part = t & 7;
        const float* qp = g_Q + ((size_t)(b*1024 + m0 + m))*1024 + h*64 + part*8;
        float4 q0 = *(const float4*)qp;
        float4 q1 = *(const float4*)(qp + 4);
        int k = part*8;
        Qs[(k+0)*32+m]=q0.x; Qs[(k+1)*32+m]=q0.y; Qs[(k+2)*32+m]=q0.z; Qs[(k+3)*32+m]=q0.w;
        Qs[(k+4)*32+m]=q1.x; Qs[(k+5)*32+m]=q1.y; Qs[(k+6)*32+m]=q1.z; Qs[(k+7)*32+m]=q1.w;
    }

    int tm4 = (t >> 5) << 2;
    int tn8 = (t & 31) << 3;
    for (int nt = 0; nt < 4; nt++) {
        int n0 = nt << 8;
        __syncthreads();
        #pragma unroll
        for (int p = 0; p < 2; p++) {
            int n = p*128 + (t >> 1), half = t & 1;
            const float* kp = g_K + ((size_t)(b*1024 + n0 + n))*1024 + h*64 + half*32;
            #pragma unroll
            for (int i = 0; i < 8; i++) {
                float4 kv = *(const float4*)(kp + i*4);
                int kk = half*32 + i*4;
                KV[(kk+0)*256+n]=kv.x; KV[(kk+1)*256+n]=kv.y;
                KV[(kk+2)*256+n]=kv.z; KV[(kk+3)*256+n]=kv.w;
            }
        }
        __syncthreads();

        ull acc[4][4];
        #pragma unroll
        for (int i = 0; i < 4; i++)
            #pragma unroll
            for (int j = 0; j < 4; j++) acc[i][j] = 0ull;

        #pragma unroll 8
        for (int k = 0; k < 64; k++) {
            float4 av = *(const float4*)&Qs[k*32 + tm4];
            const ulonglong2* bp = (const ulonglong2*)&KV[k*256 + tn8];
            ulonglong2 B0 = bp[0], B1 = bp[1];
            ull bn[4] = {B0.x, B0.y, B1.x, B1.y};
            ull am[4] = {fdup(av.x), fdup(av.y), fdup(av.z), fdup(av.w)};
            #pragma unroll
            for (int i = 0; i < 4; i++)
                #pragma unroll
                for (int j = 0; j < 4; j++)
                    ffma2(acc[i][j], am[i], bn[j]);
        }
        #pragma unroll
        for (int i = 0; i < 4; i++) {
            int m = tm4 + i;
            float fm = 0.125f * rs[m0 + m];
            float o[8];
            #pragma unroll
            for (int j = 0; j < 4; j++) {
                float2 p = funpack(acc[i][j]);
                o[2*j]   = p.x * fm * rs[n0 + tn8 + 2*j];
                o[2*j+1] = p.y * fm * rs[n0 + tn8 + 2*j + 1];
            }
            *(float4*)&S[m*1024 + n0 + tn8]     = make_float4(o[0],o[1],o[2],o[3]);
            *(float4*)&S[m*1024 + n0 + tn8 + 4] = make_float4(o[4],o[5],o[6],o[7]);
        }
    }
    __syncthreads();

    {
        int w = t >> 5, lane = t & 31;
        float* ab = attn_out + ((size_t)((b*NHEAD + h)*1024 + m0))*1024;
        for (int r = 0; r < 4; r++) {
            int m = (w << 2) + r;
            float* Sr = S + m*1024;
            float mx = -1e30f;
            #pragma unroll
            for (int c = 0; c < 32; c++) mx = fmaxf(mx, Sr[lane + (c<<5)]);
            #pragma unroll
            for (int o = 16; o > 0; o >>= 1) mx = fmaxf(mx, __shfl_xor_sync(0xffffffffu, mx, o));
            float vals[32];
            float sum = 0.0f;
            #pragma unroll
            for (int c = 0; c < 32; c++) {
                float e = exp2f((Sr[lane + (c<<5)] - mx) * 1.4426950408889634f);
                vals[c] = e; sum += e;
            }
            #pragma unroll
            for (int o = 16; o > 0; o >>= 1) sum += __shfl_xor_sync(0xffffffffu, sum, o);
            float inv = 1.0f / sum;
            float* gr = ab + (size_t)m * 1024;
            #pragma unroll
            for (int c = 0; c < 32; c++) {
                float p = vals[c] * inv;
                Sr[lane + (c<<5)] = p;
                gr[lane + (c<<5)] = p;
            }
        }
    }
    __syncthreads();

    int sub = t >> 6;
    int u   = t & 63;
    int dp4 = (u & 15) << 2;
    int mg8 = (u >> 4) << 3;
    ull acc2[8][2];
    #pragma unroll
    for (int i = 0; i < 8; i++) { acc2[i][0] = 0ull; acc2[i][1] = 0ull; }

    int vn = t & 127, vhalf = t >> 7;
    const float* vbase = g_V + ((size_t)(b*1024 + vn))*1024 + h*64 + vhalf*32;
    float4 vreg[8];
    #pragma unroll
    for (int i = 0; i < 8; i++) vreg[i] = *(const float4*)(vbase + i*4);

    for (int nt = 0; nt < 8; nt++) {
        int n0 = nt << 7;
        __syncthreads();
        {
            float* dst = KV + vn*68 + vhalf*32;
            #pragma unroll
            for (int i = 0; i < 8; i++) *(float4*)&dst[i*4] = vreg[i];
        }
        __syncthreads();
        if (nt < 7) {
            vbase += (size_t)128 * 1024;
            #pragma unroll
            for (int i = 0; i < 8; i++) vreg[i] = *(const float4*)(vbase + i*4);
        }

        #pragma unroll 4
        for (int nn = 0; nn < 32; nn++) {
            int n = sub*32 + nn;
            const ulonglong2* vp = (const ulonglong2*)&KV[n*68 + dp4];
            ulonglong2 V0 = vp[0];
            #pragma unroll
            for (int i = 0; i < 8; i++) {
                ull sd = fdup(S[(mg8 + i)*1024 + n0 + n]);
                ffma2(acc2[i][0], sd, V0.x);
                ffma2(acc2[i][1], sd, V0.y);
            }
        }
    }
    __syncthreads();

    {
        float* scr = S;
        #pragma unroll
        for (int i = 0; i < 8; i++) {
            float2 p0 = funpack(acc2[i][0]);
            float2 p1 = funpack(acc2[i][1]);
            *(float4*)&scr[sub*2048 + (mg8 + i)*64 + dp4] = make_float4(p0.x, p0.y, p1.x, p1.y);
        }
    }
    __syncthreads();
    {
        float* scr = S;
        int d = t & 63, mgr = t >> 6;
        float part = 0.0f;
        #pragma unroll
        for (int i = 0; i < 8; i++) {
            int m = mgr*8 + i;
            float c = scr[m*64 + d] + scr[2048 + m*64 + d]
                    + scr[4096 + m*64 + d] + scr[6144 + m*64 + d];
            float gv = g_G[((size_t)(b*1024 + m0 + m))*1024 + h*64 + d];
            part = fmaf(c, gv, part);
        }
        red[t] = part;
    }
    __syncthreads();
    if (t < 64) {
        float s = red[t] + red[64 + t] + red[128 + t] + red[192 + t];
        g_ctxp[(((size_t)(b*NHEAD + h))*32 + mt)*64 + t] = s;
    }
}

// =====================================================================
// Kernel 4: z = mean_m(fused) @ Wo + bo   (grid 8x16, 256 thr, k-split 4)
// =====================================================================
__global__ void z_kernel(const float* __restrict__ Wo, const float* __restrict__ bo,
                         float* __restrict__ z)
{
    __shared__ float mf[1024];
    __shared__ float red[256];
    int b = blockIdx.x, cb = blockIdx.y, t = threadIdx.x;
    for (int j = t; j < 1024; j += 256) {
        const float* p = g_ctxp + ((size_t)(b*NHEAD + (j >> 6)))*32*64 + (j & 63);
        float s = 0.0f;
        #pragma unroll
        for (int mtl = 0; mtl < 32; mtl++) s += p[mtl*64];
        mf[j] = s * (1.0f/1024.0f);
    }
    __syncthreads();
    int c = cb*64 + (t & 63);
    int kq = t >> 6;
    float a0 = 0.f, a1 = 0.f, a2 = 0.f, a3 = 0.f;
    int jb = kq * 256;
    #pragma unroll 4
    for (int jj = 0; jj < 256; jj += 4) {
        a0 = fmaf(mf[jb+jj  ], Wo[(jb+jj  )*1024 + c], a0);
        a1 = fmaf(mf[jb+jj+1], Wo[(jb+jj+1)*1024 + c], a1);
        a2 = fmaf(mf[jb+jj+2], Wo[(jb+jj+2)*1024 + c], a2);
        a3 = fmaf(mf[jb+jj+3], Wo[(jb+jj+3)*1024 + c], a3);
    }
    red[t] = (a0 + a1) + (a2 + a3);
    __syncthreads();
    if (t < 64)
        z[(size_t)b*1024 + c] = red[t] + red[64+t] + red[128+t] + red[192+t] + bo[c];
}

// =====================================================================
// launch
// =====================================================================
extern "C" void kernel_launch(void* const* d_in, const int* in_sizes, int n_in,
                              void* d_out, int out_size)
{
    const float* x   = (const float*)d_in[0];
    const float* Wq  = (const float*)d_in[1];  const float* bq  = (const float*)d_in[2];
    const float* Wk  = (const float*)d_in[3];  const float* bk  = (const float*)d_in[4];
    const float* Wv  = (const float*)d_in[5];  const float* bv  = (const float*)d_in[6];
    const float* Wg  = (const float*)d_in[7];  const float* bg  = (const float*)d_in[8];
    const float* Wo  = (const float*)d_in[9];  const float* bo  = (const float*)d_in[10];
    const float* Wu1 = (const float*)d_in[11]; const float* bu1 = (const float*)d_in[12];
    const float* Wu2 = (const float*)d_in[13]; const float* bu2 = (const float*)d_in[14];

    float* out       = (float*)d_out;
    float* z_out     = out;
    float* attn_out  = out + 8192;
    float* sigma_out = out + 8192 + (size_t)BSZ*NHEAD*MSEQ*MSEQ;

    cudaFuncSetAttribute(attn_kernel, cudaFuncAttributeMaxDynamicSharedMemorySize,
                         ATTN_SMEM_FLOATS * (int)sizeof(float));
    cudaFuncSetAttribute(mma_gemm_kernel, cudaFuncAttributeMaxDynamicSharedMemorySize,
                         GSM_TOTAL);

    split_x_kernel<<<4096, 256>>>(x);
    split_w_kernel<<<dim3(16, 32, 5), 256>>>(Wq, Wk, Wv, Wg, Wu1);
    mma_gemm_kernel<<<dim3(8, 64, 5), 256, GSM_TOTAL>>>(bq, bk, bv, bg, bu1);
    sigma_finish_kernel<<<TOK / 8, 256>>>(Wu2, bu2, sigma_out);
    attn_kernel<<<dim3(32, NHEAD, BSZ), 256, ATTN_SMEM_FLOATS * (int)sizeof(float)>>>(attn_out);
    z_kernel<<<dim3(BSZ, 16), 256>>>(Wo, bo, z_out);
}